// round 1
// baseline (speedup 1.0000x reference)
#include <cuda_runtime.h>
#include <math.h>

#define DIM 768
#define MLPD 3072
#define HEADS 12
#define DH 64
#define TOK 4096          // 4 * 1024
#define SEQ 1024
#define NB 4

// ---------------- scratch buffers (device globals; no allocation allowed) ----
__device__ float g_h[TOK * DIM];       // LN output
__device__ float g_qkv[TOK * 3 * DIM]; // qkv projections
__device__ float g_attn[TOK * DIM];    // attention output (pre o-proj)
__device__ float g_mlp[TOK * MLPD];    // MLP hidden

// ---------------- LayerNorm: one block per row --------------------------------
__global__ void layernorm_kernel(const float* __restrict__ x,
                                 const float* __restrict__ w,
                                 const float* __restrict__ b,
                                 float* __restrict__ out) {
    int row = blockIdx.x;
    const float* xr = x + (size_t)row * DIM;
    float vals[3];
    float s = 0.f, ss = 0.f;
#pragma unroll
    for (int i = 0; i < 3; ++i) {
        float v = xr[threadIdx.x + 256 * i];
        vals[i] = v;
        s += v;
        ss += v * v;
    }
#pragma unroll
    for (int o = 16; o; o >>= 1) {
        s  += __shfl_xor_sync(0xffffffffu, s, o);
        ss += __shfl_xor_sync(0xffffffffu, ss, o);
    }
    __shared__ float shs[8], shss[8];
    __shared__ float mean_s, rstd_s;
    int wid = threadIdx.x >> 5, lid = threadIdx.x & 31;
    if (lid == 0) { shs[wid] = s; shss[wid] = ss; }
    __syncthreads();
    if (threadIdx.x == 0) {
        float S = 0.f, SS = 0.f;
#pragma unroll
        for (int i = 0; i < 8; ++i) { S += shs[i]; SS += shss[i]; }
        float mean = S * (1.0f / DIM);
        float var  = SS * (1.0f / DIM) - mean * mean;
        mean_s = mean;
        rstd_s = rsqrtf(var + 1e-5f);
    }
    __syncthreads();
    float mean = mean_s, rstd = rstd_s;
    float* orow = out + (size_t)row * DIM;
#pragma unroll
    for (int i = 0; i < 3; ++i) {
        int idx = threadIdx.x + 256 * i;
        orow[idx] = (vals[i] - mean) * rstd * w[idx] + b[idx];
    }
}

// ---------------- SGEMM 128x128x16, 256 threads, 8x8 microtile ---------------
// C[M,N] = op( A[M,K] @ B[K,N] + bias ) (+ residual read from C itself)
// Requires: M%128==0, N%128==0, K%16==0  (true for all call sites)
template <bool HAS_BIAS, bool RESID, bool DO_GELU>
__global__ __launch_bounds__(256) void sgemm_kernel(
    const float* __restrict__ A, const float* __restrict__ B,
    const float* __restrict__ bias, float* __restrict__ C,
    int M, int N, int K) {
    __shared__ float As[16][132];
    __shared__ float Bs[16][132];

    const int tid = threadIdx.x;
    const int ty = tid >> 4;   // 0..15
    const int tx = tid & 15;   // 0..15

    const float* Ab = A + (size_t)(blockIdx.y * 128) * K;
    const float* Bb = B + (size_t)(blockIdx.x * 128);

    float acc[8][8];
#pragma unroll
    for (int i = 0; i < 8; ++i)
#pragma unroll
        for (int j = 0; j < 8; ++j) acc[i][j] = 0.f;

    for (int kt = 0; kt < K; kt += 16) {
#pragma unroll
        for (int i = 0; i < 2; ++i) {
            int f = tid * 2 + i;           // 0..511 float4 index
            // A tile: [128 rows][16 cols] -> store transposed As[k][m]
            int m  = f >> 2;
            int kc = (f & 3) << 2;
            float4 va = *(const float4*)&Ab[(size_t)m * K + kt + kc];
            As[kc + 0][m] = va.x;
            As[kc + 1][m] = va.y;
            As[kc + 2][m] = va.z;
            As[kc + 3][m] = va.w;
            // B tile: [16 rows][128 cols]
            int kk = f >> 5;
            int n4 = (f & 31) << 2;
            *(float4*)&Bs[kk][n4] = *(const float4*)&Bb[(size_t)(kt + kk) * N + n4];
        }
        __syncthreads();
#pragma unroll
        for (int k = 0; k < 16; ++k) {
            float a[8], bb[8];
            *(float4*)&a[0]  = *(float4*)&As[k][ty * 8];
            *(float4*)&a[4]  = *(float4*)&As[k][ty * 8 + 4];
            *(float4*)&bb[0] = *(float4*)&Bs[k][tx * 8];
            *(float4*)&bb[4] = *(float4*)&Bs[k][tx * 8 + 4];
#pragma unroll
            for (int i = 0; i < 8; ++i)
#pragma unroll
                for (int j = 0; j < 8; ++j) acc[i][j] += a[i] * bb[j];
        }
        __syncthreads();
    }

    const int row0 = blockIdx.y * 128 + ty * 8;
    const int col0 = blockIdx.x * 128 + tx * 8;
#pragma unroll
    for (int i = 0; i < 8; ++i) {
        float* crow = C + (size_t)(row0 + i) * N + col0;
        float outv[8];
#pragma unroll
        for (int j = 0; j < 8; ++j) {
            float v = acc[i][j];
            if (HAS_BIAS) v += bias[col0 + j];
            if (DO_GELU)  v = 0.5f * v * (1.0f + erff(v * 0.70710678118654752f));
            if (RESID)    v += crow[j];
            outv[j] = v;
        }
        *(float4*)&crow[0] = *(float4*)&outv[0];
        *(float4*)&crow[4] = *(float4*)&outv[4];
    }
}

// ---------------- Fused flash attention (fp32) -------------------------------
// grid: (SEQ/128, NB*HEADS), block: 128 threads, each thread owns one query row
__global__ __launch_bounds__(128) void attention_kernel(
    const float* __restrict__ qkv, float* __restrict__ out) {
    const int bh = blockIdx.y;
    const int b = bh / HEADS;
    const int h = bh % HEADS;
    const int qrow = blockIdx.x * 128 + threadIdx.x;

    const float* qb = qkv + ((size_t)(b * SEQ + qrow)) * (3 * DIM) + h * DH;
    float q[DH];
#pragma unroll
    for (int d = 0; d < DH; ++d) q[d] = qb[d] * 0.125f;  // 1/sqrt(64)

    __shared__ float Ks[64][64];
    __shared__ float Vs[64][64];

    float m = -1e30f, l = 0.f;
    float acc[DH];
#pragma unroll
    for (int d = 0; d < DH; ++d) acc[d] = 0.f;

    for (int jt = 0; jt < SEQ / 64; ++jt) {
        __syncthreads();
        const float* kb = qkv + ((size_t)(b * SEQ + jt * 64)) * (3 * DIM) + DIM + h * DH;
        const float* vb = kb + DIM;
#pragma unroll
        for (int f = 0; f < 8; ++f) {  // 1024 float4 / 128 threads = 8 each
            int idx = threadIdx.x * 8 + f;
            int r = idx >> 4;
            int c = (idx & 15) << 2;
            *(float4*)&Ks[r][c] = *(const float4*)&kb[(size_t)r * (3 * DIM) + c];
            *(float4*)&Vs[r][c] = *(const float4*)&vb[(size_t)r * (3 * DIM) + c];
        }
        __syncthreads();

#pragma unroll 1
        for (int jc = 0; jc < 64; jc += 16) {
            float s[16];
            float tmax = m;
#pragma unroll
            for (int j = 0; j < 16; ++j) {
                float sv = 0.f;
#pragma unroll
                for (int d = 0; d < DH; ++d) sv += q[d] * Ks[jc + j][d];
                s[j] = sv;
                tmax = fmaxf(tmax, sv);
            }
            float corr = __expf(m - tmax);
            m = tmax;
            l *= corr;
#pragma unroll
            for (int d = 0; d < DH; ++d) acc[d] *= corr;
#pragma unroll
            for (int j = 0; j < 16; ++j) {
                float p = __expf(s[j] - m);
                l += p;
#pragma unroll
                for (int d = 0; d < DH; ++d) acc[d] += p * Vs[jc + j][d];
            }
        }
    }
    float inv = 1.0f / l;
    float* ob = out + ((size_t)(b * SEQ + qrow)) * DIM + h * DH;
#pragma unroll
    for (int d = 0; d < DH; ++d) ob[d] = acc[d] * inv;
}

// ---------------- host side ---------------------------------------------------
extern "C" void kernel_launch(void* const* d_in, const int* in_sizes, int n_in,
                              void* d_out, int out_size) {
    const float* x      = (const float*)d_in[0];
    const float* ln1_w  = (const float*)d_in[1];
    const float* ln1_b  = (const float*)d_in[2];
    const float* w_qkv  = (const float*)d_in[3];
    const float* w_o    = (const float*)d_in[4];
    const float* b_o    = (const float*)d_in[5];
    const float* ln2_w  = (const float*)d_in[6];
    const float* ln2_b  = (const float*)d_in[7];
    const float* w1     = (const float*)d_in[8];
    const float* b1     = (const float*)d_in[9];
    const float* w2     = (const float*)d_in[10];
    const float* b2     = (const float*)d_in[11];

    float* X = (float*)d_out;

    float *pH, *pQKV, *pATT, *pMLP;
    cudaGetSymbolAddress((void**)&pH,   g_h);
    cudaGetSymbolAddress((void**)&pQKV, g_qkv);
    cudaGetSymbolAddress((void**)&pATT, g_attn);
    cudaGetSymbolAddress((void**)&pMLP, g_mlp);

    cudaMemcpyAsync(X, x, (size_t)TOK * DIM * sizeof(float),
                    cudaMemcpyDeviceToDevice);

    for (int l = 0; l < 6; ++l) {
        const float* l1w = ln1_w + l * DIM;
        const float* l1b = ln1_b + l * DIM;
        const float* wqkv = w_qkv + (size_t)l * DIM * 3 * DIM;
        const float* wo   = w_o   + (size_t)l * DIM * DIM;
        const float* bo   = b_o   + l * DIM;
        const float* l2w = ln2_w + l * DIM;
        const float* l2b = ln2_b + l * DIM;
        const float* W1 = w1 + (size_t)l * DIM * MLPD;
        const float* B1 = b1 + l * MLPD;
        const float* W2 = w2 + (size_t)l * MLPD * DIM;
        const float* B2 = b2 + l * DIM;

        // LN1
        layernorm_kernel<<<TOK, 256>>>(X, l1w, l1b, pH);
        // QKV: [4096,768] @ [768,2304]  (no bias)
        sgemm_kernel<false, false, false>
            <<<dim3(3 * DIM / 128, TOK / 128), 256>>>(pH, wqkv, nullptr, pQKV,
                                                      TOK, 3 * DIM, DIM);
        // fused attention
        attention_kernel<<<dim3(SEQ / 128, NB * HEADS), 128>>>(pQKV, pATT);
        // O-proj + bias + residual into X
        sgemm_kernel<true, true, false>
            <<<dim3(DIM / 128, TOK / 128), 256>>>(pATT, wo, bo, X,
                                                  TOK, DIM, DIM);
        // LN2
        layernorm_kernel<<<TOK, 256>>>(X, l2w, l2b, pH);
        // MLP1 + bias + exact GELU
        sgemm_kernel<true, false, true>
            <<<dim3(MLPD / 128, TOK / 128), 256>>>(pH, W1, B1, pMLP,
                                                   TOK, MLPD, DIM);
        // MLP2 + bias + residual into X
        sgemm_kernel<true, true, false>
            <<<dim3(DIM / 128, TOK / 128), 256>>>(pMLP, W2, B2, X,
                                                  TOK, DIM, MLPD);
    }
}

// round 2
// speedup vs baseline: 1.8337x; 1.8337x over previous
#include <cuda_runtime.h>
#include <math.h>
#include <stdint.h>

#define DIM 768
#define MLPD 3072
#define HEADS 12
#define DH 64
#define TOK 4096          // 4 * 1024
#define SEQ 1024
#define NB 4

// ---------------- scratch buffers (device globals; no allocation allowed) ----
__device__ float g_h[TOK * DIM];       // LN output
__device__ float g_qkv[TOK * 3 * DIM]; // qkv projections
__device__ float g_attn[TOK * DIM];    // attention output (pre o-proj)
__device__ float g_mlp[TOK * MLPD];    // MLP hidden

// ---------------- helpers ------------------------------------------------------
__device__ __forceinline__ uint32_t f2tf32(float f) {
    uint32_t u;
    asm("cvt.rna.tf32.f32 %0, %1;" : "=r"(u) : "f"(f));
    return u;
}

// ---------------- LayerNorm: one block per row --------------------------------
__global__ void layernorm_kernel(const float* __restrict__ x,
                                 const float* __restrict__ w,
                                 const float* __restrict__ b,
                                 float* __restrict__ out) {
    int row = blockIdx.x;
    const float* xr = x + (size_t)row * DIM;
    float vals[3];
    float s = 0.f, ss = 0.f;
#pragma unroll
    for (int i = 0; i < 3; ++i) {
        float v = xr[threadIdx.x + 256 * i];
        vals[i] = v;
        s += v;
        ss += v * v;
    }
#pragma unroll
    for (int o = 16; o; o >>= 1) {
        s  += __shfl_xor_sync(0xffffffffu, s, o);
        ss += __shfl_xor_sync(0xffffffffu, ss, o);
    }
    __shared__ float shs[8], shss[8];
    __shared__ float mean_s, rstd_s;
    int wid = threadIdx.x >> 5, lid = threadIdx.x & 31;
    if (lid == 0) { shs[wid] = s; shss[wid] = ss; }
    __syncthreads();
    if (threadIdx.x == 0) {
        float S = 0.f, SS = 0.f;
#pragma unroll
        for (int i = 0; i < 8; ++i) { S += shs[i]; SS += shss[i]; }
        float mean = S * (1.0f / DIM);
        float var  = SS * (1.0f / DIM) - mean * mean;
        mean_s = mean;
        rstd_s = rsqrtf(var + 1e-5f);
    }
    __syncthreads();
    float mean = mean_s, rstd = rstd_s;
    float* orow = out + (size_t)row * DIM;
#pragma unroll
    for (int i = 0; i < 3; ++i) {
        int idx = threadIdx.x + 256 * i;
        orow[idx] = (vals[i] - mean) * rstd * w[idx] + b[idx];
    }
}

// ---------------- TF32 tensor-core GEMM ---------------------------------------
// C[M,N] = op( A[M,K] @ B[K,N] + bias ) (+ residual read from C itself)
// block tile 128x128, K-tile 32, 8 warps (4x2), warp tile 32x64,
// per warp 2x8 m16n8k8 tf32 MMAs per k8-step.
// Requires M%128==0, N%128==0, K%32==0 (true at all call sites).
template <bool HAS_BIAS, bool RESID, bool DO_GELU>
__global__ __launch_bounds__(256, 2) void tf32_gemm_kernel(
    const float* __restrict__ A, const float* __restrict__ B,
    const float* __restrict__ bias, float* __restrict__ C,
    int M, int N, int K) {
    // A row-major [m][k], stride 36 words: fragment-load bank = (4m+k)%32,
    // distinct over (group 0..7, tig 0..3) -> conflict free.
    __shared__ uint32_t As[128][36];
    // B row-major [k][n], stride 136 words: bank = (8k+n)%32, distinct -> conflict free.
    __shared__ uint32_t Bs[32][136];

    const int tid   = threadIdx.x;
    const int lane  = tid & 31;
    const int wid   = tid >> 5;
    const int group = lane >> 2;   // 0..7
    const int tig   = lane & 3;    // 0..3
    const int wm0   = (wid >> 1) * 32;  // warp row offset 0..96
    const int wn0   = (wid & 1) * 64;   // warp col offset 0/64

    const float* Ab = A + (size_t)(blockIdx.y * 128) * K;
    const float* Bb = B + (size_t)(blockIdx.x * 128);

    float acc[2][8][4];
#pragma unroll
    for (int mi = 0; mi < 2; ++mi)
#pragma unroll
        for (int ni = 0; ni < 8; ++ni)
#pragma unroll
            for (int r = 0; r < 4; ++r) acc[mi][ni][r] = 0.f;

    for (int kt = 0; kt < K; kt += 32) {
        __syncthreads();
#pragma unroll
        for (int i = 0; i < 4; ++i) {
            int fi = tid + i * 256;          // float4 index 0..1023
            // A tile: 128 rows x 32 cols (8 float4/row)
            int ar  = fi >> 3;
            int ac4 = fi & 7;
            float4 va = *(const float4*)&Ab[(size_t)ar * K + kt + ac4 * 4];
            uint4 ua = make_uint4(f2tf32(va.x), f2tf32(va.y),
                                  f2tf32(va.z), f2tf32(va.w));
            *(uint4*)&As[ar][ac4 * 4] = ua;
            // B tile: 32 rows x 128 cols (32 float4/row)
            int br  = fi >> 5;
            int bc4 = fi & 31;
            float4 vb = *(const float4*)&Bb[(size_t)(kt + br) * N + bc4 * 4];
            uint4 ub = make_uint4(f2tf32(vb.x), f2tf32(vb.y),
                                  f2tf32(vb.z), f2tf32(vb.w));
            *(uint4*)&Bs[br][bc4 * 4] = ub;
        }
        __syncthreads();

#pragma unroll
        for (int kk = 0; kk < 32; kk += 8) {
            uint32_t af[2][4];
#pragma unroll
            for (int mi = 0; mi < 2; ++mi) {
                int mrow = wm0 + mi * 16 + group;
                af[mi][0] = As[mrow][kk + tig];
                af[mi][1] = As[mrow + 8][kk + tig];
                af[mi][2] = As[mrow][kk + tig + 4];
                af[mi][3] = As[mrow + 8][kk + tig + 4];
            }
#pragma unroll
            for (int ni = 0; ni < 8; ++ni) {
                uint32_t b0 = Bs[kk + tig][wn0 + ni * 8 + group];
                uint32_t b1 = Bs[kk + tig + 4][wn0 + ni * 8 + group];
#pragma unroll
                for (int mi = 0; mi < 2; ++mi) {
                    asm volatile(
                        "mma.sync.aligned.m16n8k8.row.col.f32.tf32.tf32.f32 "
                        "{%0,%1,%2,%3}, {%4,%5,%6,%7}, {%8,%9}, {%0,%1,%2,%3};"
                        : "+f"(acc[mi][ni][0]), "+f"(acc[mi][ni][1]),
                          "+f"(acc[mi][ni][2]), "+f"(acc[mi][ni][3])
                        : "r"(af[mi][0]), "r"(af[mi][1]),
                          "r"(af[mi][2]), "r"(af[mi][3]),
                          "r"(b0), "r"(b1));
                }
            }
        }
    }

    // epilogue
    const int base_m = blockIdx.y * 128 + wm0;
    const int base_n = blockIdx.x * 128 + wn0;
#pragma unroll
    for (int mi = 0; mi < 2; ++mi) {
#pragma unroll
        for (int rr = 0; rr < 2; ++rr) {
            int row = base_m + mi * 16 + rr * 8 + group;
#pragma unroll
            for (int ni = 0; ni < 8; ++ni) {
                int col = base_n + ni * 8 + tig * 2;
                float v0 = acc[mi][ni][rr * 2 + 0];
                float v1 = acc[mi][ni][rr * 2 + 1];
                if (HAS_BIAS) { v0 += bias[col]; v1 += bias[col + 1]; }
                if (DO_GELU) {
                    v0 = 0.5f * v0 * (1.0f + erff(v0 * 0.70710678118654752f));
                    v1 = 0.5f * v1 * (1.0f + erff(v1 * 0.70710678118654752f));
                }
                float* p = C + (size_t)row * N + col;
                if (RESID) {
                    float2 r = *(float2*)p;
                    v0 += r.x; v1 += r.y;
                }
                *(float2*)p = make_float2(v0, v1);
            }
        }
    }
}

// ---------------- Fused flash attention (fp32) -------------------------------
// grid: (SEQ/128, NB*HEADS), block: 128 threads, each thread owns one query row
__global__ __launch_bounds__(128) void attention_kernel(
    const float* __restrict__ qkv, float* __restrict__ out) {
    const int bh = blockIdx.y;
    const int b = bh / HEADS;
    const int h = bh % HEADS;
    const int qrow = blockIdx.x * 128 + threadIdx.x;

    const float* qb = qkv + ((size_t)(b * SEQ + qrow)) * (3 * DIM) + h * DH;
    float q[DH];
#pragma unroll
    for (int d = 0; d < DH; ++d) q[d] = qb[d] * 0.125f;  // 1/sqrt(64)

    __shared__ float Ks[64][64];
    __shared__ float Vs[64][64];

    float m = -1e30f, l = 0.f;
    float acc[DH];
#pragma unroll
    for (int d = 0; d < DH; ++d) acc[d] = 0.f;

    for (int jt = 0; jt < SEQ / 64; ++jt) {
        __syncthreads();
        const float* kb = qkv + ((size_t)(b * SEQ + jt * 64)) * (3 * DIM) + DIM + h * DH;
        const float* vb = kb + DIM;
#pragma unroll
        for (int f = 0; f < 8; ++f) {  // 1024 float4 / 128 threads = 8 each
            int idx = threadIdx.x * 8 + f;
            int r = idx >> 4;
            int c = (idx & 15) << 2;
            *(float4*)&Ks[r][c] = *(const float4*)&kb[(size_t)r * (3 * DIM) + c];
            *(float4*)&Vs[r][c] = *(const float4*)&vb[(size_t)r * (3 * DIM) + c];
        }
        __syncthreads();

#pragma unroll 1
        for (int jc = 0; jc < 64; jc += 16) {
            float s[16];
            float tmax = m;
#pragma unroll
            for (int j = 0; j < 16; ++j) {
                float sv = 0.f;
#pragma unroll
                for (int d = 0; d < DH; ++d) sv += q[d] * Ks[jc + j][d];
                s[j] = sv;
                tmax = fmaxf(tmax, sv);
            }
            float corr = __expf(m - tmax);
            m = tmax;
            l *= corr;
#pragma unroll
            for (int d = 0; d < DH; ++d) acc[d] *= corr;
#pragma unroll
            for (int j = 0; j < 16; ++j) {
                float p = __expf(s[j] - m);
                l += p;
#pragma unroll
                for (int d = 0; d < DH; ++d) acc[d] += p * Vs[jc + j][d];
            }
        }
    }
    float inv = 1.0f / l;
    float* ob = out + ((size_t)(b * SEQ + qrow)) * DIM + h * DH;
#pragma unroll
    for (int d = 0; d < DH; ++d) ob[d] = acc[d] * inv;
}

// ---------------- host side ---------------------------------------------------
extern "C" void kernel_launch(void* const* d_in, const int* in_sizes, int n_in,
                              void* d_out, int out_size) {
    const float* x      = (const float*)d_in[0];
    const float* ln1_w  = (const float*)d_in[1];
    const float* ln1_b  = (const float*)d_in[2];
    const float* w_qkv  = (const float*)d_in[3];
    const float* w_o    = (const float*)d_in[4];
    const float* b_o    = (const float*)d_in[5];
    const float* ln2_w  = (const float*)d_in[6];
    const float* ln2_b  = (const float*)d_in[7];
    const float* w1     = (const float*)d_in[8];
    const float* b1     = (const float*)d_in[9];
    const float* w2     = (const float*)d_in[10];
    const float* b2     = (const float*)d_in[11];

    float* X = (float*)d_out;

    float *pH, *pQKV, *pATT, *pMLP;
    cudaGetSymbolAddress((void**)&pH,   g_h);
    cudaGetSymbolAddress((void**)&pQKV, g_qkv);
    cudaGetSymbolAddress((void**)&pATT, g_attn);
    cudaGetSymbolAddress((void**)&pMLP, g_mlp);

    cudaMemcpyAsync(X, x, (size_t)TOK * DIM * sizeof(float),
                    cudaMemcpyDeviceToDevice);

    for (int l = 0; l < 6; ++l) {
        const float* l1w = ln1_w + l * DIM;
        const float* l1b = ln1_b + l * DIM;
        const float* wqkv = w_qkv + (size_t)l * DIM * 3 * DIM;
        const float* wo   = w_o   + (size_t)l * DIM * DIM;
        const float* bo   = b_o   + l * DIM;
        const float* l2w = ln2_w + l * DIM;
        const float* l2b = ln2_b + l * DIM;
        const float* W1 = w1 + (size_t)l * DIM * MLPD;
        const float* B1 = b1 + l * MLPD;
        const float* W2 = w2 + (size_t)l * MLPD * DIM;
        const float* B2 = b2 + l * DIM;

        // LN1
        layernorm_kernel<<<TOK, 256>>>(X, l1w, l1b, pH);
        // QKV: [4096,768] @ [768,2304]  (no bias)
        tf32_gemm_kernel<false, false, false>
            <<<dim3(3 * DIM / 128, TOK / 128), 256>>>(pH, wqkv, nullptr, pQKV,
                                                      TOK, 3 * DIM, DIM);
        // fused attention
        attention_kernel<<<dim3(SEQ / 128, NB * HEADS), 128>>>(pQKV, pATT);
        // O-proj + bias + residual into X
        tf32_gemm_kernel<true, true, false>
            <<<dim3(DIM / 128, TOK / 128), 256>>>(pATT, wo, bo, X,
                                                  TOK, DIM, DIM);
        // LN2
        layernorm_kernel<<<TOK, 256>>>(X, l2w, l2b, pH);
        // MLP1 + bias + exact GELU
        tf32_gemm_kernel<true, false, true>
            <<<dim3(MLPD / 128, TOK / 128), 256>>>(pH, W1, B1, pMLP,
                                                   TOK, MLPD, DIM);
        // MLP2 + bias + residual into X
        tf32_gemm_kernel<true, true, false>
            <<<dim3(DIM / 128, TOK / 128), 256>>>(pMLP, W2, B2, X,
                                                  TOK, DIM, MLPD);
    }
}